// round 4
// baseline (speedup 1.0000x reference)
#include <cuda_runtime.h>
#include <cstdint>

#define DT_C    0.054f
#define GAMMA_C 4.9f
#define EPS_C   4.8f

constexpr int Bn = 64, Tn = 1024, In = 256, Hn = 512;
constexpr int WROW = In + 2 * Hn;     // 1280 floats per W row
constexpr int KS   = 2 * Hn;          // 1024 state dim, interleaved (hz,hy) pairs
constexpr int NG   = 8;               // batch groups
constexpr int GC   = 16;              // CTAs per group (cluster size)
constexpr int PS   = 1028;            // smem row pitch (floats)
constexpr int PS4  = PS / 4;          // 257 float4

// Scratch: double-buffered interleaved state + fallback barrier counters.
__device__ __align__(16) float g_state[2][Bn][KS];
__device__ unsigned int g_bar[NG];

// ---------------------------------------------------------------------------
__global__ void cornn_init_kernel() {
    int i = blockIdx.x * blockDim.x + threadIdx.x;
    float* s0 = &g_state[0][0][0];
    if (i < Bn * KS) s0[i] = 0.0f;
    if (i < NG) g_bar[i] = 0u;
}

// ---------------------------------------------------------------------------
// GEMM: out[m, h] = sum_i X[m, i] * W[h, i] + bias[h]   (xs into d_out in place)
// ---------------------------------------------------------------------------
__global__ void __launch_bounds__(256) cornn_gemm_kernel(
    const float* __restrict__ X, const float* __restrict__ Wg,
    const float* __restrict__ bias, float* __restrict__ out)
{
    constexpr int BM = 128, BN = 64, BK = 16, NCH = In / BK;
    __shared__ float As[2][BK][BM + 4];
    __shared__ float Bs[2][BK][BN + 4];

    const int tid = threadIdx.x;
    const int m0 = blockIdx.x * BM;
    const int n0 = blockIdx.y * BN;
    const int tx = tid & 15;
    const int ty = tid >> 4;

    const int rowA0 = tid >> 2,         kqA0 = tid & 3;
    const int rowA1 = (tid + 256) >> 2, kqA1 = tid & 3;
    const int rowB = tid >> 2, kqB = tid & 3;

    const float4* X4 = (const float4*)X;
    const float4* W4 = (const float4*)Wg;

    float acc[8][4];
#pragma unroll
    for (int i = 0; i < 8; i++)
#pragma unroll
        for (int j = 0; j < 4; j++) acc[i][j] = 0.0f;

    float4 a0 = X4[(size_t)(m0 + rowA0) * 64 + kqA0];
    float4 a1 = X4[(size_t)(m0 + rowA1) * 64 + kqA1];
    float4 bb = W4[(size_t)(n0 + rowB) * 320 + kqB];
#pragma unroll
    for (int cc = 0; cc < 4; cc++) {
        As[0][kqA0 * 4 + cc][rowA0] = ((const float*)&a0)[cc];
        As[0][kqA1 * 4 + cc][rowA1] = ((const float*)&a1)[cc];
        Bs[0][kqB * 4 + cc][rowB]   = ((const float*)&bb)[cc];
    }
    __syncthreads();

    for (int kc = 0; kc < NCH; ++kc) {
        const int cur = kc & 1;
        float4 nA0, nA1, nB;
        if (kc + 1 < NCH) {
            nA0 = X4[(size_t)(m0 + rowA0) * 64 + (kc + 1) * 4 + kqA0];
            nA1 = X4[(size_t)(m0 + rowA1) * 64 + (kc + 1) * 4 + kqA1];
            nB  = W4[(size_t)(n0 + rowB) * 320 + (kc + 1) * 4 + kqB];
        }
#pragma unroll
        for (int kk = 0; kk < BK; ++kk) {
            float4 av0 = *(const float4*)&As[cur][kk][ty * 8];
            float4 av1 = *(const float4*)&As[cur][kk][ty * 8 + 4];
            float4 bv  = *(const float4*)&Bs[cur][kk][tx * 4];
            const float am[8] = {av0.x, av0.y, av0.z, av0.w, av1.x, av1.y, av1.z, av1.w};
            const float bn_[4] = {bv.x, bv.y, bv.z, bv.w};
#pragma unroll
            for (int i = 0; i < 8; i++)
#pragma unroll
                for (int j = 0; j < 4; j++)
                    acc[i][j] = fmaf(am[i], bn_[j], acc[i][j]);
        }
        if (kc + 1 < NCH) {
            const int nxt = cur ^ 1;
#pragma unroll
            for (int cc = 0; cc < 4; cc++) {
                As[nxt][kqA0 * 4 + cc][rowA0] = ((const float*)&nA0)[cc];
                As[nxt][kqA1 * 4 + cc][rowA1] = ((const float*)&nA1)[cc];
                Bs[nxt][kqB * 4 + cc][rowB]   = ((const float*)&nB)[cc];
            }
            __syncthreads();
        }
    }

    float4 bv = *(const float4*)&bias[n0 + tx * 4];
#pragma unroll
    for (int i = 0; i < 8; i++) {
        float4 o;
        o.x = acc[i][0] + bv.x;
        o.y = acc[i][1] + bv.y;
        o.z = acc[i][2] + bv.z;
        o.w = acc[i][3] + bv.w;
        *(float4*)&out[(size_t)(m0 + ty * 8 + i) * Hn + n0 + tx * 4] = o;
    }
}

// ---------------------------------------------------------------------------
// Persistent scan. 128 CTAs = 8 groups x 16 CTAs (cluster if supported).
// Warp = output tile (2 b-tiles x 4 h-tiles, each 4b x 8h); lane = k-part
// (ksplit 32, k-interleaved). Dot in packed f32x2; reduction = warp shuffle
// butterfly (lane l ends owning output l of its tile). State interleaved
// (hz,hy) so weights are interleaved (Wz,Wy) at the one-time smem load and
// the state publish is a single float2 STG.
// ---------------------------------------------------------------------------
template <bool CLUS>
__global__ void __launch_bounds__(256, 1) cornn_scan_kernel(
    const float* __restrict__ Wg, float* out)
{
    extern __shared__ float smem[];
    float*  Wsm  = smem;                 // 32 rows * PS
    float*  Ssm  = smem + 32 * PS;       // 8 rows * PS
    float4* Ssm4 = (float4*)Ssm;

    const int tid  = threadIdx.x;
    const int g    = blockIdx.x >> 4;
    const int c    = blockIdx.x & 15;
    const int hbase = c * 32;
    const int bbase = g * 8;
    const int lane = tid & 31;
    const int warp = tid >> 5;
    const int bt = warp & 1;    // b-tile: rows bt*4 .. bt*4+3
    const int ht = warp >> 1;   // h-tile: rows ht*8 .. ht*8+7

    // ---- one-time: load weight slice, interleaving Wz/Wy columns ----
    for (int j = 0; j < 32; ++j) {
        const float* wr = Wg + (size_t)(hbase + j) * WROW;
        float* dst = Wsm + j * PS;
#pragma unroll
        for (int h2 = tid; h2 < Hn; h2 += 256) {
            dst[2 * h2]     = wr[In + h2];        // Wz[row][h2]
            dst[2 * h2 + 1] = wr[In + Hn + h2];   // Wy[row][h2]
        }
    }
    __syncthreads();

    const unsigned s_sbase =
        (unsigned)__cvta_generic_to_shared(Ssm + bt * 4 * PS) + lane * 16;
    const unsigned s_wbase =
        (unsigned)__cvta_generic_to_shared(Wsm + ht * 8 * PS) + lane * 16;

    // final output ownership (from the butterfly: lane l -> index l of tile)
    const int bfin = bbase + bt * 4 + (lane >> 3);
    const int hfin = hbase + ht * 8 + (lane & 7);
    float hz = 0.0f, hy = 0.0f;
    const size_t obase = (size_t)bfin * Tn * Hn + hfin;

    for (int t = 0; t < Tn; ++t) {
        float xsv = out[obase + (size_t)t * Hn];   // xs (GEMM output), prefetched

        // ---- stage state slab (8 rows x 1024 f32) L2 -> smem ----
        const float4* Sg4 = (const float4*)&g_state[t & 1][bbase][0];
        float4 st[8];
#pragma unroll
        for (int r = 0; r < 8; ++r) st[r] = __ldcg(Sg4 + r * 256 + tid);
#pragma unroll
        for (int r = 0; r < 8; ++r) Ssm4[r * PS4 + tid] = st[r];
        __syncthreads();

        // ---- 4x8 packed-f32x2 dot, 8 k-quads per thread (interleaved) ----
        unsigned long long a[4][8];
#pragma unroll
        for (int i = 0; i < 4; i++)
#pragma unroll
            for (int j = 0; j < 8; j++) a[i][j] = 0ull;

        unsigned sa = s_sbase, wa = s_wbase;
#pragma unroll 2
        for (int it = 0; it < 8; ++it) {
            unsigned long long s01[4], s23[4], w01[8], w23[8];
#pragma unroll
            for (int i = 0; i < 4; i++)
                asm volatile("ld.shared.v2.u64 {%0,%1},[%2];"
                             : "=l"(s01[i]), "=l"(s23[i])
                             : "r"(sa + i * (PS * 4)));
#pragma unroll
            for (int j = 0; j < 8; j++)
                asm volatile("ld.shared.v2.u64 {%0,%1},[%2];"
                             : "=l"(w01[j]), "=l"(w23[j])
                             : "r"(wa + j * (PS * 4)));
#pragma unroll
            for (int i = 0; i < 4; i++)
#pragma unroll
                for (int j = 0; j < 8; j++) {
                    asm("fma.rn.f32x2 %0,%1,%2,%0;"
                        : "+l"(a[i][j]) : "l"(s01[i]), "l"(w01[j]));
                    asm("fma.rn.f32x2 %0,%1,%2,%0;"
                        : "+l"(a[i][j]) : "l"(s23[i]), "l"(w23[j]));
                }
            sa += 512;  // next 32-quad stride (32 * 16B)
            wa += 512;
        }

        // ---- collapse packed halves, then warp butterfly reduce ----
        float v[32];
#pragma unroll
        for (int i = 0; i < 4; i++)
#pragma unroll
            for (int j = 0; j < 8; j++) {
                float lo, hi;
                asm("mov.b64 {%0,%1},%2;" : "=f"(lo), "=f"(hi) : "l"(a[i][j]));
                v[i * 8 + j] = lo + hi;
            }
#pragma unroll
        for (int lvl = 0; lvl < 5; ++lvl) {
            const int m   = 16 >> lvl;
            const int cnt = 16 >> lvl;
            const bool hih = (lane & m) != 0;
#pragma unroll
            for (int k = 0; k < cnt; ++k) {
                float send  = hih ? v[k] : v[k + cnt];
                float other = __shfl_xor_sync(0xffffffffu, send, m);
                float keep  = hih ? v[k + cnt] : v[k];
                v[k] = keep + other;
            }
        }
        // v[0] = full dot for (bfin, hfin)

        float pre = xsv + v[0];
        float th = tanhf(pre);
        hz = hz + DT_C * (th - GAMMA_C * hy - EPS_C * hz);
        hy = hy + DT_C * hz;

        // publish state (interleaved float2), then the visible output
        ((float2*)&g_state[(t + 1) & 1][bfin][0])[hfin] = make_float2(hz, hy);
        out[obase + (size_t)t * Hn] = hy;

        // ---- group sync ----
        if constexpr (CLUS) {
            asm volatile("barrier.cluster.arrive.aligned;" ::: "memory");
            asm volatile("barrier.cluster.wait.aligned;" ::: "memory");
        } else {
            __syncthreads();
            if (tid == 0) {
                __threadfence();
                atomicAdd(&g_bar[g], 1u);
                const unsigned target = (unsigned)(GC * (t + 1));
                unsigned vv;
                do {
                    asm volatile("ld.acquire.gpu.global.u32 %0,[%1];"
                                 : "=r"(vv) : "l"(&g_bar[g]));
                } while (vv < target);
            }
            __syncthreads();
        }
    }

    // h_out (1, B, H)
    out[(size_t)Bn * Tn * Hn + (size_t)bfin * Hn + hfin] = hy;
}

// ---------------------------------------------------------------------------
extern "C" void kernel_launch(void* const* d_in, const int* in_sizes, int n_in,
                              void* d_out, int out_size)
{
    const float* x    = (const float*)d_in[0];
    const float* W    = (const float*)d_in[1];
    const float* bias = (const float*)d_in[2];
    float* out = (float*)d_out;

    const int scan_smem = (32 + 8) * PS * 4;    // 164480 bytes

    cudaFuncSetAttribute(cornn_scan_kernel<true>,
                         cudaFuncAttributeMaxDynamicSharedMemorySize, scan_smem);
    cudaFuncSetAttribute(cornn_scan_kernel<true>,
                         cudaFuncAttributeNonPortableClusterSizeAllowed, 1);
    cudaFuncSetAttribute(cornn_scan_kernel<false>,
                         cudaFuncAttributeMaxDynamicSharedMemorySize, scan_smem);

    cornn_init_kernel<<<(Bn * KS + 255) / 256, 256>>>();
    cornn_gemm_kernel<<<dim3((Bn * Tn) / 128, Hn / 64), 256>>>(x, W, bias, out);

    // probe: can we run 16-CTA clusters with this smem/block config?
    cudaLaunchConfig_t probe = {};
    probe.gridDim = dim3(NG * GC, 1, 1);
    probe.blockDim = dim3(256, 1, 1);
    probe.dynamicSmemBytes = scan_smem;
    probe.numAttrs = 0;
    int maxclus = 0;
    cudaError_t qerr = cudaOccupancyMaxPotentialClusterSize(
        &maxclus, cornn_scan_kernel<true>, &probe);

    if (qerr == cudaSuccess && maxclus >= GC) {
        cudaLaunchConfig_t cfg = {};
        cfg.gridDim = dim3(NG * GC, 1, 1);
        cfg.blockDim = dim3(256, 1, 1);
        cfg.dynamicSmemBytes = scan_smem;
        cfg.stream = 0;
        cudaLaunchAttribute at[1];
        at[0].id = cudaLaunchAttributeClusterDimension;
        at[0].val.clusterDim.x = GC;
        at[0].val.clusterDim.y = 1;
        at[0].val.clusterDim.z = 1;
        cfg.attrs = at;
        cfg.numAttrs = 1;
        cudaLaunchKernelEx(&cfg, cornn_scan_kernel<true>, W, out);
    } else {
        cornn_scan_kernel<false><<<NG * GC, 256, scan_smem>>>(W, out);
    }
}

// round 5
// speedup vs baseline: 1.5793x; 1.5793x over previous
#include <cuda_runtime.h>
#include <cstdint>

#define DT_C    0.054f
#define GAMMA_C 4.9f
#define EPS_C   4.8f

constexpr int Bn = 64, Tn = 1024, In = 256, Hn = 512;
constexpr int WROW = In + 2 * Hn;     // 1280 floats per W row
constexpr int KS   = 2 * Hn;          // 1024 state dim [hz|hy]
constexpr int NG   = 8;               // batch groups
constexpr int GC   = 16;              // CTAs per group
constexpr int PS   = 1028;            // smem row pitch (floats)
constexpr int PS4  = PS / 4;          // 257 float4

__device__ __align__(16) float g_state[2][Bn][KS];
__device__ unsigned int g_bar[NG];

// ---------------------------------------------------------------------------
__global__ void cornn_init_kernel() {
    int i = blockIdx.x * blockDim.x + threadIdx.x;
    float* s0 = &g_state[0][0][0];
    if (i < Bn * KS) s0[i] = 0.0f;
    if (i < NG) g_bar[i] = 0u;
}

// ---------------------------------------------------------------------------
// GEMM: out[m, h] = sum_i X[m, i] * W[h, i] + bias[h]
// m-dimension pairs accumulated in packed f32x2 (fma pipe halved; B splats on
// the alu pipe).
// ---------------------------------------------------------------------------
__global__ void __launch_bounds__(256) cornn_gemm_kernel(
    const float* __restrict__ X, const float* __restrict__ Wg,
    const float* __restrict__ bias, float* __restrict__ out)
{
    constexpr int BM = 128, BN = 64, BK = 16, NCH = In / BK;
    __shared__ __align__(16) float As[2][BK][BM + 4];
    __shared__ __align__(16) float Bs[2][BK][BN + 4];

    const int tid = threadIdx.x;
    const int m0 = blockIdx.x * BM;
    const int n0 = blockIdx.y * BN;
    const int tx = tid & 15;
    const int ty = tid >> 4;

    const int rowA0 = tid >> 2,         kqA0 = tid & 3;
    const int rowA1 = (tid + 256) >> 2, kqA1 = tid & 3;
    const int rowB = tid >> 2, kqB = tid & 3;

    const float4* X4 = (const float4*)X;
    const float4* W4 = (const float4*)Wg;

    // acc[ip][j] packs output rows (2ip, 2ip+1) for column j
    unsigned long long acc[4][4];
#pragma unroll
    for (int i = 0; i < 4; i++)
#pragma unroll
        for (int j = 0; j < 4; j++) acc[i][j] = 0ull;

    float4 a0 = X4[(size_t)(m0 + rowA0) * 64 + kqA0];
    float4 a1 = X4[(size_t)(m0 + rowA1) * 64 + kqA1];
    float4 bb = W4[(size_t)(n0 + rowB) * 320 + kqB];
#pragma unroll
    for (int cc = 0; cc < 4; cc++) {
        As[0][kqA0 * 4 + cc][rowA0] = ((const float*)&a0)[cc];
        As[0][kqA1 * 4 + cc][rowA1] = ((const float*)&a1)[cc];
        Bs[0][kqB * 4 + cc][rowB]   = ((const float*)&bb)[cc];
    }
    __syncthreads();

    for (int kc = 0; kc < NCH; ++kc) {
        const int cur = kc & 1;
        float4 nA0, nA1, nB;
        if (kc + 1 < NCH) {
            nA0 = X4[(size_t)(m0 + rowA0) * 64 + (kc + 1) * 4 + kqA0];
            nA1 = X4[(size_t)(m0 + rowA1) * 64 + (kc + 1) * 4 + kqA1];
            nB  = W4[(size_t)(n0 + rowB) * 320 + (kc + 1) * 4 + kqB];
        }
#pragma unroll
        for (int kk = 0; kk < BK; ++kk) {
            // A pairs: 4 u64 covering m rows ty*8 .. ty*8+7
            const ulonglong2* ap =
                (const ulonglong2*)&As[cur][kk][ty * 8];
            ulonglong2 amA = ap[0];   // (m0m1, m2m3)
            ulonglong2 amB = ap[1];   // (m4m5, m6m7)
            float4 bv = *(const float4*)&Bs[cur][kk][tx * 4];
            unsigned long long bs[4];
            asm("mov.b64 %0,{%1,%1};" : "=l"(bs[0]) : "f"(bv.x));
            asm("mov.b64 %0,{%1,%1};" : "=l"(bs[1]) : "f"(bv.y));
            asm("mov.b64 %0,{%1,%1};" : "=l"(bs[2]) : "f"(bv.z));
            asm("mov.b64 %0,{%1,%1};" : "=l"(bs[3]) : "f"(bv.w));
            const unsigned long long am[4] = {amA.x, amA.y, amB.x, amB.y};
#pragma unroll
            for (int ip = 0; ip < 4; ip++)
#pragma unroll
                for (int j = 0; j < 4; j++)
                    asm("fma.rn.f32x2 %0,%1,%2,%0;"
                        : "+l"(acc[ip][j]) : "l"(am[ip]), "l"(bs[j]));
        }
        if (kc + 1 < NCH) {
            const int nxt = cur ^ 1;
#pragma unroll
            for (int cc = 0; cc < 4; cc++) {
                As[nxt][kqA0 * 4 + cc][rowA0] = ((const float*)&nA0)[cc];
                As[nxt][kqA1 * 4 + cc][rowA1] = ((const float*)&nA1)[cc];
                Bs[nxt][kqB * 4 + cc][rowB]   = ((const float*)&nB)[cc];
            }
            __syncthreads();
        }
    }

    float4 bv = *(const float4*)&bias[n0 + tx * 4];
#pragma unroll
    for (int ip = 0; ip < 4; ip++) {
        float lo[4], hi[4];
#pragma unroll
        for (int j = 0; j < 4; j++)
            asm("mov.b64 {%0,%1},%2;" : "=f"(lo[j]), "=f"(hi[j]) : "l"(acc[ip][j]));
        float4 o0, o1;
        o0.x = lo[0] + bv.x; o0.y = lo[1] + bv.y; o0.z = lo[2] + bv.z; o0.w = lo[3] + bv.w;
        o1.x = hi[0] + bv.x; o1.y = hi[1] + bv.y; o1.z = hi[2] + bv.z; o1.w = hi[3] + bv.w;
        *(float4*)&out[(size_t)(m0 + ty * 8 + 2 * ip)     * Hn + n0 + tx * 4] = o0;
        *(float4*)&out[(size_t)(m0 + ty * 8 + 2 * ip + 1) * Hn + n0 + tx * 4] = o1;
    }
}

// ---------------------------------------------------------------------------
// Persistent scan: 128 CTAs, 8 groups x 16 CTAs. CTA holds 32 W rows in smem.
// Thread = (tile=tid>>4, kp=tid&15): 4b x 4h partial dots over a 16-way
// interleaved k-split. Reduction = half-warp shuffle butterfly (the 16
// k-parts of a tile are exactly one half-warp); lane kp ends owning output
// kp of its tile. No smem reduction, 3 syncthreads/step total.
// ---------------------------------------------------------------------------
__global__ void __launch_bounds__(256, 1) cornn_scan_kernel(
    const float* __restrict__ Wg, float* out)
{
    extern __shared__ float smem[];
    float*  Wsm  = smem;                 // 32 rows * PS floats
    float4* Wsm4 = (float4*)Wsm;
    float*  Ssm  = smem + 32 * PS;       // 8 rows * PS floats
    float4* Ssm4 = (float4*)Ssm;

    const int tid  = threadIdx.x;
    const int g    = blockIdx.x >> 4;
    const int c    = blockIdx.x & 15;
    const int hbase = c * 32;
    const int bbase = g * 8;
    const int lane = tid & 31;

    const int tile = tid >> 4;          // 0..15
    const int kp   = tid & 15;          // k-part 0..15
    const int bt   = tile & 1;          // b-tile: rows bt*4..bt*4+3
    const int ht   = tile >> 1;         // h-tile: rows ht*4..ht*4+3

    // ---- resident weight slice (once) ----
    {
        const float4* W4 = (const float4*)Wg;
#pragma unroll 4
        for (int j = 0; j < 32; ++j)
            Wsm4[j * PS4 + tid] = W4[(size_t)(hbase + j) * (WROW / 4) + (In / 4) + tid];
    }
    __syncthreads();

    const unsigned s_sbase =
        (unsigned)__cvta_generic_to_shared(Ssm + bt * 4 * PS) + kp * 16;
    const unsigned s_wbase =
        (unsigned)__cvta_generic_to_shared(Wsm + ht * 4 * PS) + kp * 16;

    // final-output ownership: butterfly leaves lane kp owning output kp of tile
    const int bfin = bbase + bt * 4 + (kp >> 2);
    const int hfin = hbase + ht * 4 + (kp & 3);
    float hz = 0.0f, hy = 0.0f;
    const size_t obase = (size_t)bfin * Tn * Hn + hfin;

    for (int t = 0; t < Tn; ++t) {
        // ---- stage state slab (8 rows x 1024) L2 -> smem; xs prefetch ----
        const float4* Sg4 = (const float4*)&g_state[t & 1][bbase][0];
        float4 st[8];
#pragma unroll
        for (int r = 0; r < 8; ++r) st[r] = __ldcg(Sg4 + r * 256 + tid);
        float xsv = __ldcg(&out[obase + (size_t)t * Hn]);
#pragma unroll
        for (int r = 0; r < 8; ++r) Ssm4[r * PS4 + tid] = st[r];
        __syncthreads();

        // ---- 4x4 packed-f32x2 dot, interleaved k-split ----
        unsigned long long a[4][4];
#pragma unroll
        for (int i = 0; i < 4; i++)
#pragma unroll
            for (int j = 0; j < 4; j++) a[i][j] = 0ull;

        unsigned sa = s_sbase, wa = s_wbase;
#pragma unroll 4
        for (int q = 0; q < 16; ++q) {
            unsigned long long s01[4], s23[4], w01[4], w23[4];
#pragma unroll
            for (int i = 0; i < 4; i++)
                asm volatile("ld.shared.v2.u64 {%0,%1},[%2];"
                             : "=l"(s01[i]), "=l"(s23[i])
                             : "r"(sa + i * (PS * 4)));
#pragma unroll
            for (int j = 0; j < 4; j++)
                asm volatile("ld.shared.v2.u64 {%0,%1},[%2];"
                             : "=l"(w01[j]), "=l"(w23[j])
                             : "r"(wa + j * (PS * 4)));
#pragma unroll
            for (int i = 0; i < 4; i++)
#pragma unroll
                for (int j = 0; j < 4; j++) {
                    asm("fma.rn.f32x2 %0,%1,%2,%0;"
                        : "+l"(a[i][j]) : "l"(s01[i]), "l"(w01[j]));
                    asm("fma.rn.f32x2 %0,%1,%2,%0;"
                        : "+l"(a[i][j]) : "l"(s23[i]), "l"(w23[j]));
                }
            sa += 256;
            wa += 256;
        }

        // ---- collapse packed halves -> v[16], then half-warp butterfly ----
        float v[16];
#pragma unroll
        for (int i = 0; i < 4; i++)
#pragma unroll
            for (int j = 0; j < 4; j++) {
                float lo, hi;
                asm("mov.b64 {%0,%1},%2;" : "=f"(lo), "=f"(hi) : "l"(a[i][j]));
                v[i * 4 + j] = lo + hi;
            }
#pragma unroll
        for (int lvl = 0; lvl < 4; ++lvl) {
            const int m = 8 >> lvl;          // 8,4,2,1 (= live count)
            const bool hih = (lane & m) != 0;
#pragma unroll
            for (int k = 0; k < 8; ++k) {
                if (k >= m) break;           // fully unrolled: compile-time
                float send  = hih ? v[k] : v[k + m];
                float other = __shfl_xor_sync(0xffffffffu, send, m);
                float keep  = hih ? v[k + m] : v[k];
                v[k] = keep + other;
            }
        }
        // v[0] = full dot for (bfin, hfin)

        float pre = xsv + v[0];
        float th = tanhf(pre);
        hz = hz + DT_C * (th - GAMMA_C * hy - EPS_C * hz);
        hy = hy + DT_C * hz;

        out[obase + (size_t)t * Hn] = hy;

        float* Sw = &g_state[(t + 1) & 1][bfin][0];
        Sw[hfin]      = hz;
        Sw[Hn + hfin] = hy;

        // ---- group barrier (atomic counter) ----
        __syncthreads();
        if (tid == 0) {
            __threadfence();
            atomicAdd(&g_bar[g], 1u);
            const unsigned target = (unsigned)(GC * (t + 1));
            unsigned vv;
            do {
                asm volatile("ld.acquire.gpu.global.u32 %0,[%1];"
                             : "=r"(vv) : "l"(&g_bar[g]));
            } while (vv < target);
        }
        __syncthreads();
    }

    // h_out (1, B, H)
    out[(size_t)Bn * Tn * Hn + (size_t)bfin * Hn + hfin] = hy;
}

// ---------------------------------------------------------------------------
extern "C" void kernel_launch(void* const* d_in, const int* in_sizes, int n_in,
                              void* d_out, int out_size)
{
    const float* x    = (const float*)d_in[0];
    const float* W    = (const float*)d_in[1];
    const float* bias = (const float*)d_in[2];
    float* out = (float*)d_out;

    const int scan_smem = (32 + 8) * PS * 4;    // 164480 bytes
    cudaFuncSetAttribute(cornn_scan_kernel,
                         cudaFuncAttributeMaxDynamicSharedMemorySize, scan_smem);

    cornn_init_kernel<<<(Bn * KS + 255) / 256, 256>>>();
    cornn_gemm_kernel<<<dim3((Bn * Tn) / 128, Hn / 64), 256>>>(x, W, bias, out);
    cornn_scan_kernel<<<NG * GC, 256, scan_smem>>>(W, out);
}

// round 6
// speedup vs baseline: 1.5909x; 1.0073x over previous
#include <cuda_runtime.h>
#include <cstdint>

#define DT_C    0.054f
#define GAMMA_C 4.9f
#define EPS_C   4.8f

constexpr int Bn = 64, Tn = 1024, In = 256, Hn = 512;
constexpr int WROW = In + 2 * Hn;     // 1280 floats per W row
constexpr int KS   = 2 * Hn;          // 1024 state dim [hz|hy]
constexpr int NG   = 8;               // batch groups
constexpr int GC   = 16;              // CTAs per group
constexpr int PS   = 1028;            // smem row pitch (floats)
constexpr int PS4  = PS / 4;          // 257 float4

// Double-buffered state + per-CTA epoch flags (128B apart: no LTS clash).
__device__ __align__(16) float g_state[2][Bn][KS];
__device__ __align__(128) unsigned int g_flags[NG][GC * 32];

// ---------------------------------------------------------------------------
// GEMM (+ embedded init of scan scratch): out[m,h] = X[m,:]·W[h,:256] + b[h]
// ---------------------------------------------------------------------------
__global__ void __launch_bounds__(256) cornn_gemm_kernel(
    const float* __restrict__ X, const float* __restrict__ Wg,
    const float* __restrict__ bias, float* __restrict__ out)
{
    // ---- embedded init (safe: scan launches after this kernel completes) ----
    if (blockIdx.y == 0 && blockIdx.x < 64) {
        ((float4*)&g_state[0][0][0])[blockIdx.x * 256 + threadIdx.x] =
            make_float4(0.f, 0.f, 0.f, 0.f);
    }
    if (blockIdx.y == 1 && blockIdx.x < 16) {
        (&g_flags[0][0])[blockIdx.x * 256 + threadIdx.x] = 0u;
    }

    constexpr int BM = 128, BN = 64, BK = 16, NCH = In / BK;
    __shared__ __align__(16) float As[2][BK][BM + 4];
    __shared__ __align__(16) float Bs[2][BK][BN + 4];

    const int tid = threadIdx.x;
    const int m0 = blockIdx.x * BM;
    const int n0 = blockIdx.y * BN;
    const int tx = tid & 15;
    const int ty = tid >> 4;

    const int rowA0 = tid >> 2,         kqA0 = tid & 3;
    const int rowA1 = (tid + 256) >> 2, kqA1 = tid & 3;
    const int rowB = tid >> 2, kqB = tid & 3;

    const float4* X4 = (const float4*)X;
    const float4* W4 = (const float4*)Wg;

    unsigned long long acc[4][4];
#pragma unroll
    for (int i = 0; i < 4; i++)
#pragma unroll
        for (int j = 0; j < 4; j++) acc[i][j] = 0ull;

    float4 a0 = X4[(size_t)(m0 + rowA0) * 64 + kqA0];
    float4 a1 = X4[(size_t)(m0 + rowA1) * 64 + kqA1];
    float4 bb = W4[(size_t)(n0 + rowB) * 320 + kqB];
#pragma unroll
    for (int cc = 0; cc < 4; cc++) {
        As[0][kqA0 * 4 + cc][rowA0] = ((const float*)&a0)[cc];
        As[0][kqA1 * 4 + cc][rowA1] = ((const float*)&a1)[cc];
        Bs[0][kqB * 4 + cc][rowB]   = ((const float*)&bb)[cc];
    }
    __syncthreads();

    for (int kc = 0; kc < NCH; ++kc) {
        const int cur = kc & 1;
        float4 nA0, nA1, nB;
        if (kc + 1 < NCH) {
            nA0 = X4[(size_t)(m0 + rowA0) * 64 + (kc + 1) * 4 + kqA0];
            nA1 = X4[(size_t)(m0 + rowA1) * 64 + (kc + 1) * 4 + kqA1];
            nB  = W4[(size_t)(n0 + rowB) * 320 + (kc + 1) * 4 + kqB];
        }
#pragma unroll
        for (int kk = 0; kk < BK; ++kk) {
            const ulonglong2* ap = (const ulonglong2*)&As[cur][kk][ty * 8];
            ulonglong2 amA = ap[0];
            ulonglong2 amB = ap[1];
            float4 bv = *(const float4*)&Bs[cur][kk][tx * 4];
            unsigned long long bs[4];
            asm("mov.b64 %0,{%1,%1};" : "=l"(bs[0]) : "f"(bv.x));
            asm("mov.b64 %0,{%1,%1};" : "=l"(bs[1]) : "f"(bv.y));
            asm("mov.b64 %0,{%1,%1};" : "=l"(bs[2]) : "f"(bv.z));
            asm("mov.b64 %0,{%1,%1};" : "=l"(bs[3]) : "f"(bv.w));
            const unsigned long long am[4] = {amA.x, amA.y, amB.x, amB.y};
#pragma unroll
            for (int ip = 0; ip < 4; ip++)
#pragma unroll
                for (int j = 0; j < 4; j++)
                    asm("fma.rn.f32x2 %0,%1,%2,%0;"
                        : "+l"(acc[ip][j]) : "l"(am[ip]), "l"(bs[j]));
        }
        if (kc + 1 < NCH) {
            const int nxt = cur ^ 1;
#pragma unroll
            for (int cc = 0; cc < 4; cc++) {
                As[nxt][kqA0 * 4 + cc][rowA0] = ((const float*)&nA0)[cc];
                As[nxt][kqA1 * 4 + cc][rowA1] = ((const float*)&nA1)[cc];
                Bs[nxt][kqB * 4 + cc][rowB]   = ((const float*)&nB)[cc];
            }
            __syncthreads();
        }
    }

    float4 bv = *(const float4*)&bias[n0 + tx * 4];
#pragma unroll
    for (int ip = 0; ip < 4; ip++) {
        float lo[4], hi[4];
#pragma unroll
        for (int j = 0; j < 4; j++)
            asm("mov.b64 {%0,%1},%2;" : "=f"(lo[j]), "=f"(hi[j]) : "l"(acc[ip][j]));
        float4 o0, o1;
        o0.x = lo[0] + bv.x; o0.y = lo[1] + bv.y; o0.z = lo[2] + bv.z; o0.w = lo[3] + bv.w;
        o1.x = hi[0] + bv.x; o1.y = hi[1] + bv.y; o1.z = hi[2] + bv.z; o1.w = hi[3] + bv.w;
        *(float4*)&out[(size_t)(m0 + ty * 8 + 2 * ip)     * Hn + n0 + tx * 4] = o0;
        *(float4*)&out[(size_t)(m0 + ty * 8 + 2 * ip + 1) * Hn + n0 + tx * 4] = o1;
    }
}

// ---------------------------------------------------------------------------
// Persistent scan: 128 CTAs, 8 groups x 16 CTAs. 4b x 4h tiles, ksplit 16,
// half-warp shuffle reduction. Distributed epoch-flag barrier: arrival is a
// single st.release to the CTA's own 128B-strided slot; warp 0 lanes 0-15
// poll all 16 slots in parallel with ld.acquire + ballot. out-store and
// xs(t+1) prefetch overlap the poll.
// ---------------------------------------------------------------------------
__global__ void __launch_bounds__(256, 1) cornn_scan_kernel(
    const float* __restrict__ Wg, float* out)
{
    extern __shared__ float smem[];
    float*  Wsm  = smem;                 // 32 rows * PS floats
    float4* Wsm4 = (float4*)Wsm;
    float*  Ssm  = smem + 32 * PS;       // 8 rows * PS floats
    float4* Ssm4 = (float4*)Ssm;

    const int tid  = threadIdx.x;
    const int g    = blockIdx.x >> 4;
    const int c    = blockIdx.x & 15;
    const int hbase = c * 32;
    const int bbase = g * 8;
    const int lane = tid & 31;

    const int tile = tid >> 4;          // 0..15
    const int kp   = tid & 15;          // k-part 0..15
    const int bt   = tile & 1;
    const int ht   = tile >> 1;

    // ---- resident weight slice (once) ----
    {
        const float4* W4 = (const float4*)Wg;
#pragma unroll 4
        for (int j = 0; j < 32; ++j)
            Wsm4[j * PS4 + tid] = W4[(size_t)(hbase + j) * (WROW / 4) + (In / 4) + tid];
    }
    __syncthreads();

    const unsigned s_sbase =
        (unsigned)__cvta_generic_to_shared(Ssm + bt * 4 * PS) + kp * 16;
    const unsigned s_wbase =
        (unsigned)__cvta_generic_to_shared(Wsm + ht * 4 * PS) + kp * 16;

    const int bfin = bbase + bt * 4 + (kp >> 2);
    const int hfin = hbase + ht * 4 + (kp & 3);
    float hz = 0.0f, hy = 0.0f;
    const size_t obase = (size_t)bfin * Tn * Hn + hfin;

    unsigned int* const my_slot   = &g_flags[g][c * 32];
    unsigned int* const poll_slot = &g_flags[g][(tid < GC ? tid : 0) * 32];

    float xs_next = __ldcg(&out[obase]);   // xs for t = 0

    for (int t = 0; t < Tn; ++t) {
        const float xsv = xs_next;

        // ---- stage state slab (8 rows x 1024) L2 -> smem ----
        const float4* Sg4 = (const float4*)&g_state[t & 1][bbase][0];
        float4 st[8];
#pragma unroll
        for (int r = 0; r < 8; ++r) st[r] = __ldcg(Sg4 + r * 256 + tid);
#pragma unroll
        for (int r = 0; r < 8; ++r) Ssm4[r * PS4 + tid] = st[r];
        __syncthreads();

        // ---- 4x4 packed-f32x2 dot, interleaved k-split ----
        unsigned long long a[4][4];
#pragma unroll
        for (int i = 0; i < 4; i++)
#pragma unroll
            for (int j = 0; j < 4; j++) a[i][j] = 0ull;

        unsigned sa = s_sbase, wa = s_wbase;
#pragma unroll 4
        for (int q = 0; q < 16; ++q) {
            unsigned long long s01[4], s23[4], w01[4], w23[4];
#pragma unroll
            for (int i = 0; i < 4; i++)
                asm volatile("ld.shared.v2.u64 {%0,%1},[%2];"
                             : "=l"(s01[i]), "=l"(s23[i])
                             : "r"(sa + i * (PS * 4)));
#pragma unroll
            for (int j = 0; j < 4; j++)
                asm volatile("ld.shared.v2.u64 {%0,%1},[%2];"
                             : "=l"(w01[j]), "=l"(w23[j])
                             : "r"(wa + j * (PS * 4)));
#pragma unroll
            for (int i = 0; i < 4; i++)
#pragma unroll
                for (int j = 0; j < 4; j++) {
                    asm("fma.rn.f32x2 %0,%1,%2,%0;"
                        : "+l"(a[i][j]) : "l"(s01[i]), "l"(w01[j]));
                    asm("fma.rn.f32x2 %0,%1,%2,%0;"
                        : "+l"(a[i][j]) : "l"(s23[i]), "l"(w23[j]));
                }
            sa += 256;
            wa += 256;
        }

        // ---- collapse packed halves -> v[16], half-warp butterfly ----
        float v[16];
#pragma unroll
        for (int i = 0; i < 4; i++)
#pragma unroll
            for (int j = 0; j < 4; j++) {
                float lo, hi;
                asm("mov.b64 {%0,%1},%2;" : "=f"(lo), "=f"(hi) : "l"(a[i][j]));
                v[i * 4 + j] = lo + hi;
            }
#pragma unroll
        for (int lvl = 0; lvl < 4; ++lvl) {
            const int m = 8 >> lvl;
            const bool hih = (lane & m) != 0;
#pragma unroll
            for (int k = 0; k < 8; ++k) {
                if (k >= m) break;
                float send  = hih ? v[k] : v[k + m];
                float other = __shfl_xor_sync(0xffffffffu, send, m);
                float keep  = hih ? v[k + m] : v[k];
                v[k] = keep + other;
            }
        }

        const float pre = xsv + v[0];
        const float th = tanhf(pre);
        hz = hz + DT_C * (th - GAMMA_C * hy - EPS_C * hz);
        hy = hy + DT_C * hz;

        // publish state first (this is what peers wait for)
        float* Sw = &g_state[(t + 1) & 1][bfin][0];
        Sw[hfin]      = hz;
        Sw[Hn + hfin] = hy;

        __syncthreads();                 // all state STGs issued
        if (tid == 0) {
            asm volatile("st.release.gpu.global.u32 [%0],%1;"
                         :: "l"(my_slot), "r"((unsigned)(t + 1)) : "memory");
        }

        // overlap with the poll: visible output + next xs prefetch
        out[obase + (size_t)t * Hn] = hy;
        if (t + 1 < Tn) xs_next = __ldcg(&out[obase + (size_t)(t + 1) * Hn]);

        if (tid < GC) {
            bool mine = false;
            unsigned vv;
            do {
                if (!mine) {
                    asm volatile("ld.acquire.gpu.global.u32 %0,[%1];"
                                 : "=r"(vv) : "l"(poll_slot));
                    mine = (vv >= (unsigned)(t + 1));
                }
            } while (__ballot_sync(0x0000ffffu, mine) != 0x0000ffffu);
        }
        __syncthreads();
    }

    // h_out (1, B, H)
    out[(size_t)Bn * Tn * Hn + (size_t)bfin * Hn + hfin] = hy;
}

// ---------------------------------------------------------------------------
extern "C" void kernel_launch(void* const* d_in, const int* in_sizes, int n_in,
                              void* d_out, int out_size)
{
    const float* x    = (const float*)d_in[0];
    const float* W    = (const float*)d_in[1];
    const float* bias = (const float*)d_in[2];
    float* out = (float*)d_out;

    const int scan_smem = (32 + 8) * PS * 4;    // 164480 bytes
    cudaFuncSetAttribute(cornn_scan_kernel,
                         cudaFuncAttributeMaxDynamicSharedMemorySize, scan_smem);

    cornn_gemm_kernel<<<dim3((Bn * Tn) / 128, Hn / 64), 256>>>(x, W, bias, out);
    cornn_scan_kernel<<<NG * GC, 256, scan_smem>>>(W, out);
}

// round 7
// speedup vs baseline: 1.8184x; 1.1430x over previous
#include <cuda_runtime.h>
#include <cstdint>

#define DT_C    0.054f
#define GAMMA_C 4.9f
#define EPS_C   4.8f

constexpr int Bn = 64, Tn = 1024, In = 256, Hn = 512;
constexpr int WROW = In + 2 * Hn;     // 1280 floats per W row
constexpr int KS   = 2 * Hn;          // 1024 state dim [hz|hy]
constexpr int NG   = 8;               // batch groups
constexpr int GC   = 16;              // CTAs per group
constexpr int PS   = 1028;            // smem row pitch (floats)
constexpr int PS4  = PS / 4;          // 257 float4
constexpr int SCT  = 512;             // scan threads per CTA
constexpr int RP   = 528;             // red pitch per p-slice (floats)
constexpr int SREG = 8448;            // staging/red region floats (16*528)

// Double-buffered state + per-CTA epoch flags (128B apart: no LTS clash).
__device__ __align__(16) float g_state[2][Bn][KS];
__device__ __align__(128) unsigned int g_flags[NG][GC * 32];

// ---------------------------------------------------------------------------
// GEMM (+ embedded init of scan scratch): out[m,h] = X[m,:]·W[h,:256] + b[h]
// ---------------------------------------------------------------------------
__global__ void __launch_bounds__(256) cornn_gemm_kernel(
    const float* __restrict__ X, const float* __restrict__ Wg,
    const float* __restrict__ bias, float* __restrict__ out)
{
    if (blockIdx.y == 0 && blockIdx.x < 64) {
        ((float4*)&g_state[0][0][0])[blockIdx.x * 256 + threadIdx.x] =
            make_float4(0.f, 0.f, 0.f, 0.f);
    }
    if (blockIdx.y == 1 && blockIdx.x < 16) {
        (&g_flags[0][0])[blockIdx.x * 256 + threadIdx.x] = 0u;
    }

    constexpr int BM = 128, BN = 64, BK = 16, NCH = In / BK;
    __shared__ __align__(16) float As[2][BK][BM + 4];
    __shared__ __align__(16) float Bs[2][BK][BN + 4];

    const int tid = threadIdx.x;
    const int m0 = blockIdx.x * BM;
    const int n0 = blockIdx.y * BN;
    const int tx = tid & 15;
    const int ty = tid >> 4;

    const int rowA0 = tid >> 2,         kqA0 = tid & 3;
    const int rowA1 = (tid + 256) >> 2, kqA1 = tid & 3;
    const int rowB = tid >> 2, kqB = tid & 3;

    const float4* X4 = (const float4*)X;
    const float4* W4 = (const float4*)Wg;

    unsigned long long acc[4][4];
#pragma unroll
    for (int i = 0; i < 4; i++)
#pragma unroll
        for (int j = 0; j < 4; j++) acc[i][j] = 0ull;

    float4 a0 = X4[(size_t)(m0 + rowA0) * 64 + kqA0];
    float4 a1 = X4[(size_t)(m0 + rowA1) * 64 + kqA1];
    float4 bb = W4[(size_t)(n0 + rowB) * 320 + kqB];
#pragma unroll
    for (int cc = 0; cc < 4; cc++) {
        As[0][kqA0 * 4 + cc][rowA0] = ((const float*)&a0)[cc];
        As[0][kqA1 * 4 + cc][rowA1] = ((const float*)&a1)[cc];
        Bs[0][kqB * 4 + cc][rowB]   = ((const float*)&bb)[cc];
    }
    __syncthreads();

    for (int kc = 0; kc < NCH; ++kc) {
        const int cur = kc & 1;
        float4 nA0, nA1, nB;
        if (kc + 1 < NCH) {
            nA0 = X4[(size_t)(m0 + rowA0) * 64 + (kc + 1) * 4 + kqA0];
            nA1 = X4[(size_t)(m0 + rowA1) * 64 + (kc + 1) * 4 + kqA1];
            nB  = W4[(size_t)(n0 + rowB) * 320 + (kc + 1) * 4 + kqB];
        }
#pragma unroll
        for (int kk = 0; kk < BK; ++kk) {
            const ulonglong2* ap = (const ulonglong2*)&As[cur][kk][ty * 8];
            ulonglong2 amA = ap[0];
            ulonglong2 amB = ap[1];
            float4 bv = *(const float4*)&Bs[cur][kk][tx * 4];
            unsigned long long bs[4];
            asm("mov.b64 %0,{%1,%1};" : "=l"(bs[0]) : "f"(bv.x));
            asm("mov.b64 %0,{%1,%1};" : "=l"(bs[1]) : "f"(bv.y));
            asm("mov.b64 %0,{%1,%1};" : "=l"(bs[2]) : "f"(bv.z));
            asm("mov.b64 %0,{%1,%1};" : "=l"(bs[3]) : "f"(bv.w));
            const unsigned long long am[4] = {amA.x, amA.y, amB.x, amB.y};
#pragma unroll
            for (int ip = 0; ip < 4; ip++)
#pragma unroll
                for (int j = 0; j < 4; j++)
                    asm("fma.rn.f32x2 %0,%1,%2,%0;"
                        : "+l"(acc[ip][j]) : "l"(am[ip]), "l"(bs[j]));
        }
        if (kc + 1 < NCH) {
            const int nxt = cur ^ 1;
#pragma unroll
            for (int cc = 0; cc < 4; cc++) {
                As[nxt][kqA0 * 4 + cc][rowA0] = ((const float*)&nA0)[cc];
                As[nxt][kqA1 * 4 + cc][rowA1] = ((const float*)&nA1)[cc];
                Bs[nxt][kqB * 4 + cc][rowB]   = ((const float*)&nB)[cc];
            }
            __syncthreads();
        }
    }

    float4 bv = *(const float4*)&bias[n0 + tx * 4];
#pragma unroll
    for (int ip = 0; ip < 4; ip++) {
        float lo[4], hi[4];
#pragma unroll
        for (int j = 0; j < 4; j++)
            asm("mov.b64 {%0,%1},%2;" : "=f"(lo[j]), "=f"(hi[j]) : "l"(acc[ip][j]));
        float4 o0, o1;
        o0.x = lo[0] + bv.x; o0.y = lo[1] + bv.y; o0.z = lo[2] + bv.z; o0.w = lo[3] + bv.w;
        o1.x = hi[0] + bv.x; o1.y = hi[1] + bv.y; o1.z = hi[2] + bv.z; o1.w = hi[3] + bv.w;
        *(float4*)&out[(size_t)(m0 + ty * 8 + 2 * ip)     * Hn + n0 + tx * 4] = o0;
        *(float4*)&out[(size_t)(m0 + ty * 8 + 2 * ip + 1) * Hn + n0 + tx * 4] = o1;
    }
}

// ---------------------------------------------------------------------------
// Persistent scan: 128 CTAs (8 groups x 16), 512 threads each (16 warps).
// thread = (kp = tid>>4 in 0..31, tile = tid&15); tile -> (bt=tile&1, ht=tile>>1),
// each tile = 4b x 4h. Low-bit tile => heavy broadcast dedup: s-load 1cyc,
// w-load 2cyc per instr. W rows permuted in smem (row a -> (a>>2)+(a&3)*8)
// for conflict-free 4-row access. ksplit-32 partials reduced via conflict-free
// smem buffer red[p][kp][tile] aliased over the staging slab. Output o = tid
// (<256). Epoch-flag group barrier.
// ---------------------------------------------------------------------------
__global__ void __launch_bounds__(SCT, 1) cornn_scan_kernel(
    const float* __restrict__ Wg, float* out)
{
    extern __shared__ float smem[];
    float*  Wsm  = smem;                       // 32 rows * PS floats
    float4* Wsm4 = (float4*)Wsm;
    float*  Ssm  = smem + 32 * PS;             // staging: 8 rows * PS floats
    float4* Ssm4 = (float4*)Ssm;
    float*  red  = Ssm;                        // aliased: [p][kp*16 + tile], pitch RP

    const int tid  = threadIdx.x;
    const int g    = blockIdx.x >> 4;
    const int c    = blockIdx.x & 15;
    const int hbase = c * 32;
    const int bbase = g * 8;

    const int tile = tid & 15;
    const int kp   = tid >> 4;          // 0..31
    const int bt   = tile & 1;
    const int ht   = tile >> 1;

    // ---- resident weight slice (once), rows permuted: a -> (a>>2)+(a&3)*8 ----
    {
        const float4* W4 = (const float4*)Wg;
        const int col = tid & 255;
        const int half = tid >> 8;      // 0 or 1: rows split
#pragma unroll
        for (int jj = 0; jj < 16; ++jj) {
            int a = half * 16 + jj;
            int rs = (a >> 2) + (a & 3) * 8;
            Wsm4[rs * PS4 + col] = W4[(size_t)(hbase + a) * (WROW / 4) + (In / 4) + col];
        }
    }
    __syncthreads();

    const unsigned s_sbase =
        (unsigned)__cvta_generic_to_shared(Ssm) + (unsigned)(bt * 4 * PS * 4) + kp * 16;
    const unsigned s_wbase =
        (unsigned)__cvta_generic_to_shared(Wsm) + (unsigned)(ht * PS * 4) + kp * 16;
    const unsigned s_red =
        (unsigned)__cvta_generic_to_shared(red);

    // output ownership: thread o = tid (<256): b = bt*4 + (p>>2), h = ht*4 + (p&3)
    const int p_o  = tid >> 4;          // for tid<256: 0..15
    const int bfin = bbase + bt * 4 + (p_o >> 2);
    const int hfin = hbase + ht * 4 + (p_o & 3);
    float hz = 0.0f, hy = 0.0f;
    const size_t obase = (size_t)bfin * Tn * Hn + hfin;

    unsigned int* const my_slot   = &g_flags[g][c * 32];
    unsigned int* const poll_slot = &g_flags[g][(tid < GC ? tid : 0) * 32];

    // staging assignment: 4 rows per thread
    const int srow0 = (tid >> 8) * 4;   // 0 or 4
    const int scol  = tid & 255;

    float xs_next = (tid < 256) ? __ldcg(&out[obase]) : 0.0f;

    for (int t = 0; t < Tn; ++t) {
        const float xsv = xs_next;

        // ---- stage state slab (8 rows x 1024) L2 -> smem ----
        const float4* Sg4 = (const float4*)&g_state[t & 1][bbase][0];
        float4 st[4];
#pragma unroll
        for (int r = 0; r < 4; ++r)
            st[r] = __ldcg(Sg4 + (srow0 + r) * 256 + scol);
#pragma unroll
        for (int r = 0; r < 4; ++r)
            Ssm4[(srow0 + r) * PS4 + scol] = st[r];
        __syncthreads();

        // ---- 4x4 packed-f32x2 dot; this thread's quads: kp + 32*it ----
        unsigned long long a[4][4];
#pragma unroll
        for (int i = 0; i < 4; i++)
#pragma unroll
            for (int j = 0; j < 4; j++) a[i][j] = 0ull;

        unsigned sa = s_sbase, wa = s_wbase;
#pragma unroll 2
        for (int it = 0; it < 8; ++it) {
            unsigned long long s01[4], s23[4], w01[4], w23[4];
#pragma unroll
            for (int i = 0; i < 4; i++)
                asm volatile("ld.shared.v2.u64 {%0,%1},[%2];"
                             : "=l"(s01[i]), "=l"(s23[i])
                             : "r"(sa + i * (PS * 4)));
#pragma unroll
            for (int j = 0; j < 4; j++)
                asm volatile("ld.shared.v2.u64 {%0,%1},[%2];"
                             : "=l"(w01[j]), "=l"(w23[j])
                             : "r"(wa + j * (8 * PS * 4)));
#pragma unroll
            for (int i = 0; i < 4; i++)
#pragma unroll
                for (int j = 0; j < 4; j++) {
                    asm("fma.rn.f32x2 %0,%1,%2,%0;"
                        : "+l"(a[i][j]) : "l"(s01[i]), "l"(w01[j]));
                    asm("fma.rn.f32x2 %0,%1,%2,%0;"
                        : "+l"(a[i][j]) : "l"(s23[i]), "l"(w23[j]));
                }
            sa += 512;     // 32 quads * 16B per it
            wa += 512;
        }
        __syncthreads();   // dot reads of Ssm done (red aliases it)

        // ---- write 16 partials: red[p][kp*16 + tile] ----
#pragma unroll
        for (int i = 0; i < 4; i++)
#pragma unroll
            for (int j = 0; j < 4; j++) {
                float lo, hi;
                asm("mov.b64 {%0,%1},%2;" : "=f"(lo), "=f"(hi) : "l"(a[i][j]));
                float pv = lo + hi;
                int p = i * 4 + j;
                asm volatile("st.shared.f32 [%0],%1;"
                             :: "r"(s_red + (unsigned)((p * RP + kp * 16 + tile) * 4)),
                                "f"(pv));
            }
        __syncthreads();

        if (tid < 256) {
            // ---- reduce 32 partials for output o = tid ----
            const unsigned rb = s_red + (unsigned)((p_o * RP + tile) * 4);
            float q0 = 0.f, q1 = 0.f, q2 = 0.f, q3 = 0.f;
#pragma unroll
            for (int k = 0; k < 32; k += 4) {
                float r0, r1, r2, r3;
                asm volatile("ld.shared.f32 %0,[%1];" : "=f"(r0) : "r"(rb + (k + 0) * 64));
                asm volatile("ld.shared.f32 %0,[%1];" : "=f"(r1) : "r"(rb + (k + 1) * 64));
                asm volatile("ld.shared.f32 %0,[%1];" : "=f"(r2) : "r"(rb + (k + 2) * 64));
                asm volatile("ld.shared.f32 %0,[%1];" : "=f"(r3) : "r"(rb + (k + 3) * 64));
                q0 += r0; q1 += r1; q2 += r2; q3 += r3;
            }
            const float pre = xsv + ((q0 + q1) + (q2 + q3));
            const float th = tanhf(pre);
            hz = hz + DT_C * (th - GAMMA_C * hy - EPS_C * hz);
            hy = hy + DT_C * hz;

            // publish state (what peers wait for)
            float* Sw = &g_state[(t + 1) & 1][bfin][0];
            Sw[hfin]      = hz;
            Sw[Hn + hfin] = hy;
        }

        __syncthreads();                 // all state STGs issued, red reads done
        if (tid == 0) {
            asm volatile("st.release.gpu.global.u32 [%0],%1;"
                         :: "l"(my_slot), "r"((unsigned)(t + 1)) : "memory");
        }

        // overlap with the poll: visible output + next xs prefetch
        if (tid < 256) {
            out[obase + (size_t)t * Hn] = hy;
            if (t + 1 < Tn) xs_next = __ldcg(&out[obase + (size_t)(t + 1) * Hn]);
        }

        if (tid < GC) {
            bool mine = false;
            unsigned vv;
            do {
                if (!mine) {
                    asm volatile("ld.acquire.gpu.global.u32 %0,[%1];"
                                 : "=r"(vv) : "l"(poll_slot));
                    mine = (vv >= (unsigned)(t + 1));
                }
            } while (__ballot_sync(0x0000ffffu, mine) != 0x0000ffffu);
        }
        __syncthreads();
    }

    // h_out (1, B, H)
    if (tid < 256)
        out[(size_t)Bn * Tn * Hn + (size_t)bfin * Hn + hfin] = hy;
}

// ---------------------------------------------------------------------------
extern "C" void kernel_launch(void* const* d_in, const int* in_sizes, int n_in,
                              void* d_out, int out_size)
{
    const float* x    = (const float*)d_in[0];
    const float* W    = (const float*)d_in[1];
    const float* bias = (const float*)d_in[2];
    float* out = (float*)d_out;

    const int scan_smem = (32 * PS + SREG) * 4;   // 165376 bytes
    cudaFuncSetAttribute(cornn_scan_kernel,
                         cudaFuncAttributeMaxDynamicSharedMemorySize, scan_smem);

    cornn_gemm_kernel<<<dim3((Bn * Tn) / 128, Hn / 64), 256>>>(x, W, bias, out);
    cornn_scan_kernel<<<NG * GC, SCT, scan_smem>>>(W, out);
}